// round 12
// baseline (speedup 1.0000x reference)
#include <cuda_runtime.h>
#include <cuda_fp16.h>

#define N_NODES 100000
#define N_EDGES 1600000
#define IN_CH 128
#define HID 32
#define CAP 128          // ELL row capacity (max deg ~40 on this input)
#define NB_BUILD ((N_EDGES + 255) / 256)
#define FULL 0xffffffffu

// ---------------- scratch (device globals; no allocation allowed) ----------
// g_yh / g_uh / g_t have one extra ZERO row at index N_NODES (sentinel for
// ELL padding). It is never written, so it stays .bss-zero forever.
__device__ float  g_y [N_NODES * HID];          // x @ w1a (fp32 self term)
__device__ __half g_yh[(N_NODES + 1) * HID];    // fp16 copy for gathers (+zero row)
__device__ float  g_a1[N_NODES * HID];          // layer-1 aggregated (pre-MLP)
__device__ float  g_u [N_NODES * HID];          // layer-2 features (fp32 self term)
__device__ __half g_uh[(N_NODES + 1) * HID];    // fp16 copy for gathers (+zero row)
__device__ float  g_t [N_NODES + 1];            // scalar layer-3 pre-agg (+zero)
__device__ int    g_ell[N_NODES * CAP];
__device__ int    g_deg[N_NODES];               // PADDED degree after pad_ell
__device__ float  g_W12[HID * HID];             // w1b @ w2a
__device__ float  g_B12[HID];                   // b1b @ w2a
__device__ float  g_Wv [HID];                   // w2b @ w3
__device__ float  g_bv;                         // b2b . w3

// ---------------- ELL build + (last block) weight fusion --------------------
__global__ void __launch_bounds__(256) build_ell(
        const int* __restrict__ ei,
        const float* __restrict__ w1b, const float* __restrict__ w2a,
        const float* __restrict__ b1b, const float* __restrict__ w2b,
        const float* __restrict__ w3,  const float* __restrict__ b2b) {
    if (blockIdx.x == NB_BUILD) {    // weight-fusion block
        int j = threadIdx.x & 31;
        #pragma unroll
        for (int r = 0; r < 4; r++) {
            int i = (threadIdx.x >> 5) + r * 8;
            float s = 0.f;
            #pragma unroll
            for (int m = 0; m < HID; m++) s += w1b[i * HID + m] * w2a[m * HID + j];
            g_W12[i * HID + j] = s;
        }
        if (threadIdx.x < 32) {
            float b = 0.f;
            #pragma unroll
            for (int m = 0; m < HID; m++) b += b1b[m] * w2a[m * HID + j];
            g_B12[j] = b;
            float wv = 0.f;
            #pragma unroll
            for (int m = 0; m < HID; m++) wv += w2b[j * HID + m] * w3[m];
            g_Wv[j] = wv;
            if (j == 0) {
                float bb = 0.f;
                #pragma unroll
                for (int m = 0; m < HID; m++) bb += b2b[m] * w3[m];
                g_bv = bb;
            }
        }
        return;
    }
    int e = blockIdx.x * 256 + threadIdx.x;
    if (e < N_EDGES) {
        int s = ei[e];
        int d = ei[N_EDGES + e];
        int p = atomicAdd(&g_deg[d], 1);
        if (p < CAP) g_ell[d * CAP + p] = s;
    }
}

// ---------------- pad rows to multiple of 8 with zero-node sentinel ---------
__global__ void __launch_bounds__(256) pad_ell() {
    int n = blockIdx.x * 256 + threadIdx.x;
    if (n >= N_NODES) return;
    int d  = min(g_deg[n], CAP);
    int dp = min((d + 7) & ~7, CAP);
    for (int k = d; k < dp; k++) g_ell[n * CAP + k] = N_NODES;
    g_deg[n] = dp;
}

// ---------------- K1: y = x @ w1a (fp32 + fp16 copies) ---------------------
__global__ void __launch_bounds__(256) gemm1(const float* __restrict__ x,
                                             const float* __restrict__ w1a) {
    __shared__ float xs[256][33];
    __shared__ float ws[HID * HID];
    const int tid   = threadIdx.x;
    const int node0 = blockIdx.x * 256;
    const int cb    = (tid & 3) * 8;
    const int ng    = tid >> 2;

    float acc[4][8];
    #pragma unroll
    for (int a = 0; a < 4; a++)
        #pragma unroll
        for (int c = 0; c < 8; c++) acc[a][c] = 0.f;

    for (int kc = 0; kc < IN_CH / 32; kc++) {
        __syncthreads();
        ((float4*)ws)[tid] = ((const float4*)(w1a + kc * 32 * HID))[tid];
        #pragma unroll
        for (int i = 0; i < 8; i++) {
            int f    = tid + 256 * i;
            int node = f >> 3;
            int col4 = f & 7;
            int gn   = node0 + node;
            float4 v = make_float4(0.f, 0.f, 0.f, 0.f);
            if (gn < N_NODES)
                v = *(const float4*)(x + (long long)gn * IN_CH + kc * 32 + col4 * 4);
            float* d = &xs[node][col4 * 4];
            d[0] = v.x; d[1] = v.y; d[2] = v.z; d[3] = v.w;
        }
        __syncthreads();
        #pragma unroll
        for (int k = 0; k < 32; k++) {
            float xv[4];
            #pragma unroll
            for (int a = 0; a < 4; a++) xv[a] = xs[ng * 4 + a][k];
            #pragma unroll
            for (int c = 0; c < 8; c++) {
                float wv = ws[k * HID + cb + c];
                #pragma unroll
                for (int a = 0; a < 4; a++) acc[a][c] += xv[a] * wv;
            }
        }
    }
    #pragma unroll
    for (int a = 0; a < 4; a++) {
        int gn = node0 + ng * 4 + a;
        if (gn < N_NODES) {
            int o = gn * HID + cb;
            *(float4*)(g_y + o)     = make_float4(acc[a][0], acc[a][1], acc[a][2], acc[a][3]);
            *(float4*)(g_y + o + 4) = make_float4(acc[a][4], acc[a][5], acc[a][6], acc[a][7]);
            __half2 h0 = __floats2half2_rn(acc[a][0], acc[a][1]);
            __half2 h1 = __floats2half2_rn(acc[a][2], acc[a][3]);
            __half2 h2 = __floats2half2_rn(acc[a][4], acc[a][5]);
            __half2 h3 = __floats2half2_rn(acc[a][6], acc[a][7]);
            uint4 hp;
            hp.x = *(unsigned*)&h0; hp.y = *(unsigned*)&h1;
            hp.z = *(unsigned*)&h2; hp.w = *(unsigned*)&h3;
            *(uint4*)(g_yh + o) = hp;
        }
    }
}

// ---------------- branch-light fp16 gather (rows padded to 8) --------------
// lane = g*8 + j. dp is a multiple of 8; padding slots hold node N_NODES
// whose feature row is all zeros. No predicates in the hot path.
__device__ __forceinline__ float4 gather4h(const __half* __restrict__ feat,
                                           const int* __restrict__ row,
                                           int dp, int lane, int g, int j) {
    float4 acc = make_float4(0.f, 0.f, 0.f, 0.f);
    for (int base = 0; base < dp; base += 32) {
        int idx = __ldg(row + base + lane);      // always in-bounds (CAP row)
        int m = min(32, dp - base);              // multiple of 8
        for (int b = 0; b < m; b += 8) {
            int s0 = __shfl_sync(FULL, idx, b + g);
            int s1 = __shfl_sync(FULL, idx, b + 4 + g);
            uint2 p0 = __ldcg((const uint2*)(feat + s0 * HID + j * 4));
            uint2 p1 = __ldcg((const uint2*)(feat + s1 * HID + j * 4));
            __half2 h0 = __hadd2(*(__half2*)&p0.x, *(__half2*)&p1.x);
            __half2 h1 = __hadd2(*(__half2*)&p0.y, *(__half2*)&p1.y);
            float2 f0 = __half22float2(h0);
            float2 f1 = __half22float2(h1);
            acc.x += f0.x; acc.y += f0.y; acc.z += f1.x; acc.w += f1.y;
        }
    }
    return acc;
}

__device__ __forceinline__ void xor_reduce4(float4& a) {
    a.x += __shfl_xor_sync(FULL, a.x, 8);
    a.y += __shfl_xor_sync(FULL, a.y, 8);
    a.z += __shfl_xor_sync(FULL, a.z, 8);
    a.w += __shfl_xor_sync(FULL, a.w, 8);
    a.x += __shfl_xor_sync(FULL, a.x, 16);
    a.y += __shfl_xor_sync(FULL, a.y, 16);
    a.z += __shfl_xor_sync(FULL, a.z, 16);
    a.w += __shfl_xor_sync(FULL, a.w, 16);
}

// ---------------- layer-1 aggregation ONLY: a1 = y[n] + sum y[src] ---------
__global__ void __launch_bounds__(256) agg1() {
    int n    = blockIdx.x * 8 + (threadIdx.x >> 5);
    int lane = threadIdx.x & 31;
    int g    = lane >> 3;
    int j    = lane & 7;
    if (n >= N_NODES) return;

    int dp = g_deg[n];
    float4 acc = gather4h(g_yh, g_ell + n * CAP, dp, lane, g, j);
    if (g == 0) {  // self term fp32, once
        float4 v = *(const float4*)(g_y + n * HID + j * 4);
        acc.x += v.x; acc.y += v.y; acc.z += v.z; acc.w += v.w;
    }
    xor_reduce4(acc);
    if (g == 0)    // lanes 0..7 write 128B coalesced
        *(float4*)(g_a1 + n * HID + j * 4) = acc;
}

// ---------------- GEMM-structured MLP: u = relu(a1+b1a)@W12 + B12 ----------
__global__ void __launch_bounds__(256) mlp1(const float* __restrict__ b1a) {
    __shared__ float xs[256][33];
    __shared__ float ws[HID * HID];
    __shared__ float sbb[HID];
    __shared__ float sb1[HID];
    const int tid   = threadIdx.x;
    const int node0 = blockIdx.x * 256;

    ((float4*)ws)[tid] = ((const float4*)g_W12)[tid];
    if (tid < HID) { sbb[tid] = g_B12[tid]; sb1[tid] = b1a[tid]; }
    __syncthreads();

    #pragma unroll
    for (int i = 0; i < 8; i++) {
        int f    = tid + 256 * i;
        int node = f >> 3;
        int col4 = f & 7;
        int gn   = node0 + node;
        float4 v = make_float4(0.f, 0.f, 0.f, 0.f);
        if (gn < N_NODES) {
            v = *(const float4*)(g_a1 + gn * HID + col4 * 4);
            v.x = fmaxf(v.x + sb1[col4 * 4 + 0], 0.f);
            v.y = fmaxf(v.y + sb1[col4 * 4 + 1], 0.f);
            v.z = fmaxf(v.z + sb1[col4 * 4 + 2], 0.f);
            v.w = fmaxf(v.w + sb1[col4 * 4 + 3], 0.f);
        }
        float* dd = &xs[node][col4 * 4];
        dd[0] = v.x; dd[1] = v.y; dd[2] = v.z; dd[3] = v.w;
    }
    __syncthreads();

    const int cb = (tid & 3) * 8;
    const int ng = tid >> 2;
    float acc[4][8];
    #pragma unroll
    for (int a = 0; a < 4; a++)
        #pragma unroll
        for (int c = 0; c < 8; c++) acc[a][c] = sbb[cb + c];

    #pragma unroll
    for (int k = 0; k < 32; k++) {
        float xv[4];
        #pragma unroll
        for (int a = 0; a < 4; a++) xv[a] = xs[ng * 4 + a][k];
        #pragma unroll
        for (int c = 0; c < 8; c++) {
            float wv = ws[k * HID + cb + c];
            #pragma unroll
            for (int a = 0; a < 4; a++) acc[a][c] += xv[a] * wv;
        }
    }
    #pragma unroll
    for (int a = 0; a < 4; a++) {
        int gn = node0 + ng * 4 + a;
        if (gn < N_NODES) {
            int o = gn * HID + cb;
            *(float4*)(g_u + o)     = make_float4(acc[a][0], acc[a][1], acc[a][2], acc[a][3]);
            *(float4*)(g_u + o + 4) = make_float4(acc[a][4], acc[a][5], acc[a][6], acc[a][7]);
            __half2 h0 = __floats2half2_rn(acc[a][0], acc[a][1]);
            __half2 h1 = __floats2half2_rn(acc[a][2], acc[a][3]);
            __half2 h2 = __floats2half2_rn(acc[a][4], acc[a][5]);
            __half2 h3 = __floats2half2_rn(acc[a][6], acc[a][7]);
            uint4 hp;
            hp.x = *(unsigned*)&h0; hp.y = *(unsigned*)&h1;
            hp.z = *(unsigned*)&h2; hp.w = *(unsigned*)&h3;
            *(uint4*)(g_uh + o) = hp;
        }
    }
}

// ---------------- fused gather-agg + scalar head, layer 2 ------------------
__global__ void __launch_bounds__(256) agg_mlp2(const float* __restrict__ b2a) {
    int n    = blockIdx.x * 8 + (threadIdx.x >> 5);
    int lane = threadIdx.x & 31;
    int g    = lane >> 3;
    int j    = lane & 7;
    if (n >= N_NODES) return;

    float4 b2 = *(const float4*)(b2a + j * 4);
    float4 wv = *(const float4*)(g_Wv + j * 4);

    int dp = g_deg[n];
    float4 acc = gather4h(g_uh, g_ell + n * CAP, dp, lane, g, j);
    if (g == 0) {
        float4 v = *(const float4*)(g_u + n * HID + j * 4);
        acc.x += v.x; acc.y += v.y; acc.z += v.z; acc.w += v.w;
    }
    xor_reduce4(acc);

    float p = fmaxf(acc.x + b2.x, 0.f) * wv.x
            + fmaxf(acc.y + b2.y, 0.f) * wv.y
            + fmaxf(acc.z + b2.z, 0.f) * wv.z
            + fmaxf(acc.w + b2.w, 0.f) * wv.w;
    p += __shfl_xor_sync(FULL, p, 1);
    p += __shfl_xor_sync(FULL, p, 2);
    p += __shfl_xor_sync(FULL, p, 4);
    if (lane == 0) g_t[n] = p + g_bv;
}

// ---------------- final scalar gather: out = t[n] + sum t[src] + b3 --------
// padded slots gather t[N_NODES] == 0 (harmless)
__global__ void __launch_bounds__(256) agg_final(const float* __restrict__ b3,
                                                 float* __restrict__ out) {
    int n    = blockIdx.x * 8 + (threadIdx.x >> 5);
    int lane = threadIdx.x & 31;
    if (n >= N_NODES) return;
    int dp = g_deg[n];
    const int* row = g_ell + n * CAP;
    float acc = 0.f;
    for (int i = lane; i < dp; i += 32) acc += __ldg(g_t + __ldg(row + i));
    #pragma unroll
    for (int o = 16; o > 0; o >>= 1)
        acc += __shfl_xor_sync(FULL, acc, o);
    if (lane == 0) out[n] = g_t[n] + acc + b3[0];
}

// ---------------- launch ---------------------------------------------------
extern "C" void kernel_launch(void* const* d_in, const int* in_sizes, int n_in,
                              void* d_out, int out_size) {
    const float* x   = (const float*)d_in[0];
    const int*   ei  = (const int*)d_in[1];
    const float* w1a = (const float*)d_in[2];
    const float* b1a = (const float*)d_in[3];
    const float* w1b = (const float*)d_in[4];
    const float* b1b = (const float*)d_in[5];
    const float* w2a = (const float*)d_in[6];
    const float* b2a = (const float*)d_in[7];
    const float* w2b = (const float*)d_in[8];
    const float* b2b = (const float*)d_in[9];
    const float* w3  = (const float*)d_in[10];
    const float* b3  = (const float*)d_in[11];
    float* out = (float*)d_out;

    void* deg_ptr = nullptr;
    cudaGetSymbolAddress(&deg_ptr, g_deg);
    cudaMemsetAsync(deg_ptr, 0, N_NODES * sizeof(int));

    build_ell<<<NB_BUILD + 1, 256>>>(ei, w1b, w2a, b1b, w2b, w3, b2b);
    pad_ell<<<(N_NODES + 255) / 256, 256>>>();
    gemm1<<<(N_NODES + 255) / 256, 256>>>(x, w1a);
    agg1<<<(N_NODES + 7) / 8, 256>>>();
    mlp1<<<(N_NODES + 255) / 256, 256>>>(b1a);
    agg_mlp2<<<(N_NODES + 7) / 8, 256>>>(b2a);
    agg_final<<<(N_NODES + 7) / 8, 256>>>(b3, out);
}

// round 13
// speedup vs baseline: 1.1323x; 1.1323x over previous
#include <cuda_runtime.h>
#include <cuda_fp16.h>

#define N_NODES 100000
#define N_EDGES 1600000
#define IN_CH 128
#define HID 32
#define CAP 128          // ELL row capacity (max deg ~40 on this input)
#define NB_BUILD ((N_EDGES + 255) / 256)
#define FULL 0xffffffffu

// ---------------- scratch (device globals; no allocation allowed) ----------
__device__ float  g_y [N_NODES * HID];    // x @ w1a (fp32: self term)
__device__ __half g_yh[N_NODES * HID];    // fp16 copy for gathers
__device__ float  g_a1[N_NODES * HID];    // layer-1 aggregated (pre-MLP)
__device__ float  g_u [N_NODES * HID];    // layer-2 features (fp32: self term)
__device__ __half g_uh[N_NODES * HID];    // fp16 copy for gathers
__device__ float  g_t [N_NODES];          // scalar layer-3 pre-agg
__device__ int    g_ell[N_NODES * CAP];
__device__ int    g_deg[N_NODES];
__device__ float  g_W12[HID * HID];       // w1b @ w2a
__device__ float  g_B12[HID];             // b1b @ w2a
__device__ float  g_Wv [HID];             // w2b @ w3
__device__ float  g_bv;                   // b2b . w3

// ---------------- ELL build + (last block) weight fusion --------------------
__global__ void __launch_bounds__(256) build_ell(
        const int* __restrict__ ei,
        const float* __restrict__ w1b, const float* __restrict__ w2a,
        const float* __restrict__ b1b, const float* __restrict__ w2b,
        const float* __restrict__ w3,  const float* __restrict__ b2b) {
    if (blockIdx.x == NB_BUILD) {    // weight-fusion block
        int j = threadIdx.x & 31;
        #pragma unroll
        for (int r = 0; r < 4; r++) {
            int i = (threadIdx.x >> 5) + r * 8;
            float s = 0.f;
            #pragma unroll
            for (int m = 0; m < HID; m++) s += w1b[i * HID + m] * w2a[m * HID + j];
            g_W12[i * HID + j] = s;
        }
        if (threadIdx.x < 32) {
            float b = 0.f;
            #pragma unroll
            for (int m = 0; m < HID; m++) b += b1b[m] * w2a[m * HID + j];
            g_B12[j] = b;
            float wv = 0.f;
            #pragma unroll
            for (int m = 0; m < HID; m++) wv += w2b[j * HID + m] * w3[m];
            g_Wv[j] = wv;
            if (j == 0) {
                float bb = 0.f;
                #pragma unroll
                for (int m = 0; m < HID; m++) bb += b2b[m] * w3[m];
                g_bv = bb;
            }
        }
        return;
    }
    int e = blockIdx.x * 256 + threadIdx.x;
    if (e < N_EDGES) {
        int s = ei[e];
        int d = ei[N_EDGES + e];
        int p = atomicAdd(&g_deg[d], 1);
        if (p < CAP) g_ell[d * CAP + p] = s;
    }
}

// ---------------- K1: y = x @ w1a (fp32 + fp16 copies) ---------------------
__global__ void __launch_bounds__(256) gemm1(const float* __restrict__ x,
                                             const float* __restrict__ w1a) {
    __shared__ float xs[256][33];
    __shared__ float ws[HID * HID];
    const int tid   = threadIdx.x;
    const int node0 = blockIdx.x * 256;
    const int cb    = (tid & 3) * 8;
    const int ng    = tid >> 2;

    float acc[4][8];
    #pragma unroll
    for (int a = 0; a < 4; a++)
        #pragma unroll
        for (int c = 0; c < 8; c++) acc[a][c] = 0.f;

    for (int kc = 0; kc < IN_CH / 32; kc++) {
        __syncthreads();
        ((float4*)ws)[tid] = ((const float4*)(w1a + kc * 32 * HID))[tid];
        #pragma unroll
        for (int i = 0; i < 8; i++) {
            int f    = tid + 256 * i;
            int node = f >> 3;
            int col4 = f & 7;
            int gn   = node0 + node;
            float4 v = make_float4(0.f, 0.f, 0.f, 0.f);
            if (gn < N_NODES)
                v = *(const float4*)(x + (long long)gn * IN_CH + kc * 32 + col4 * 4);
            float* d = &xs[node][col4 * 4];
            d[0] = v.x; d[1] = v.y; d[2] = v.z; d[3] = v.w;
        }
        __syncthreads();
        #pragma unroll
        for (int k = 0; k < 32; k++) {
            float xv[4];
            #pragma unroll
            for (int a = 0; a < 4; a++) xv[a] = xs[ng * 4 + a][k];
            #pragma unroll
            for (int c = 0; c < 8; c++) {
                float wv = ws[k * HID + cb + c];
                #pragma unroll
                for (int a = 0; a < 4; a++) acc[a][c] += xv[a] * wv;
            }
        }
    }
    #pragma unroll
    for (int a = 0; a < 4; a++) {
        int gn = node0 + ng * 4 + a;
        if (gn < N_NODES) {
            int o = gn * HID + cb;
            *(float4*)(g_y + o)     = make_float4(acc[a][0], acc[a][1], acc[a][2], acc[a][3]);
            *(float4*)(g_y + o + 4) = make_float4(acc[a][4], acc[a][5], acc[a][6], acc[a][7]);
            __half2 h0 = __floats2half2_rn(acc[a][0], acc[a][1]);
            __half2 h1 = __floats2half2_rn(acc[a][2], acc[a][3]);
            __half2 h2 = __floats2half2_rn(acc[a][4], acc[a][5]);
            __half2 h3 = __floats2half2_rn(acc[a][6], acc[a][7]);
            uint4 hp;
            hp.x = *(unsigned*)&h0; hp.y = *(unsigned*)&h1;
            hp.z = *(unsigned*)&h2; hp.w = *(unsigned*)&h3;
            *(uint4*)(g_yh + o) = hp;
        }
    }
}

// ---------------- fp16 gather with pair-wise HADD2 pre-reduction -----------
// lane = g*8 + j. Partial float4 acc per (g,j); caller xor-reduces over g.
__device__ __forceinline__ float4 gather4h(const __half* __restrict__ feat,
                                           const int* __restrict__ row,
                                           int d, int lane, int g, int j) {
    float4 acc = make_float4(0.f, 0.f, 0.f, 0.f);
    for (int base = 0; base < d; base += 32) {
        int cnt = min(32, d - base);
        int idx = (base + lane < d) ? __ldg(row + base + lane) : 0;
        int b = 0;
        for (; b + 8 <= cnt; b += 8) {
            int s0 = __shfl_sync(FULL, idx, b + g);
            int s1 = __shfl_sync(FULL, idx, b + 4 + g);
            uint2 p0 = __ldcg((const uint2*)(feat + s0 * HID + j * 4));
            uint2 p1 = __ldcg((const uint2*)(feat + s1 * HID + j * 4));
            __half2 h0 = __hadd2(*(__half2*)&p0.x, *(__half2*)&p1.x);
            __half2 h1 = __hadd2(*(__half2*)&p0.y, *(__half2*)&p1.y);
            float2 f0 = __half22float2(h0);
            float2 f1 = __half22float2(h1);
            acc.x += f0.x; acc.y += f0.y; acc.z += f1.x; acc.w += f1.y;
        }
        for (; b + 4 <= cnt; b += 4) {
            int s = __shfl_sync(FULL, idx, b + g);
            uint2 p = __ldcg((const uint2*)(feat + s * HID + j * 4));
            float2 a0 = __half22float2(*(__half2*)&p.x);
            float2 a1 = __half22float2(*(__half2*)&p.y);
            acc.x += a0.x; acc.y += a0.y; acc.z += a1.x; acc.w += a1.y;
        }
        int rem = cnt - b;
        if (rem > 0) {
            int s = __shfl_sync(FULL, idx, b + (g < rem ? g : 0));
            if (g < rem) {
                uint2 p = __ldcg((const uint2*)(feat + s * HID + j * 4));
                float2 a0 = __half22float2(*(__half2*)&p.x);
                float2 a1 = __half22float2(*(__half2*)&p.y);
                acc.x += a0.x; acc.y += a0.y; acc.z += a1.x; acc.w += a1.y;
            }
        }
    }
    return acc;
}

__device__ __forceinline__ void xor_reduce4(float4& a) {
    a.x += __shfl_xor_sync(FULL, a.x, 8);
    a.y += __shfl_xor_sync(FULL, a.y, 8);
    a.z += __shfl_xor_sync(FULL, a.z, 8);
    a.w += __shfl_xor_sync(FULL, a.w, 8);
    a.x += __shfl_xor_sync(FULL, a.x, 16);
    a.y += __shfl_xor_sync(FULL, a.y, 16);
    a.z += __shfl_xor_sync(FULL, a.z, 16);
    a.w += __shfl_xor_sync(FULL, a.w, 16);
}

#define NODES_PER_WARP 4

// ---------------- layer-1 aggregation ONLY: a1 = y[n] + sum y[src] ---------
// each warp handles 4 consecutive nodes (load-balance: sum-of-4 degrees)
__global__ void __launch_bounds__(256) agg1() {
    int warp0 = blockIdx.x * 8 + (threadIdx.x >> 5);
    int lane  = threadIdx.x & 31;
    int g     = lane >> 3;
    int j     = lane & 7;
    int n0    = warp0 * NODES_PER_WARP;

    #pragma unroll
    for (int q = 0; q < NODES_PER_WARP; q++) {
        int n = n0 + q;
        if (n >= N_NODES) return;
        int d = g_deg[n];
        float4 acc = gather4h(g_yh, g_ell + n * CAP, d, lane, g, j);
        if (g == 0) {
            float4 v = *(const float4*)(g_y + n * HID + j * 4);
            acc.x += v.x; acc.y += v.y; acc.z += v.z; acc.w += v.w;
        }
        xor_reduce4(acc);
        if (g == 0)
            *(float4*)(g_a1 + n * HID + j * 4) = acc;
    }
}

// ---------------- GEMM-structured MLP: u = relu(a1+b1a)@W12 + B12 ----------
__global__ void __launch_bounds__(256) mlp1(const float* __restrict__ b1a) {
    __shared__ float xs[256][33];
    __shared__ float ws[HID * HID];
    __shared__ float sbb[HID];
    __shared__ float sb1[HID];
    const int tid   = threadIdx.x;
    const int node0 = blockIdx.x * 256;

    ((float4*)ws)[tid] = ((const float4*)g_W12)[tid];
    if (tid < HID) { sbb[tid] = g_B12[tid]; sb1[tid] = b1a[tid]; }
    __syncthreads();

    #pragma unroll
    for (int i = 0; i < 8; i++) {
        int f    = tid + 256 * i;
        int node = f >> 3;
        int col4 = f & 7;
        int gn   = node0 + node;
        float4 v = make_float4(0.f, 0.f, 0.f, 0.f);
        if (gn < N_NODES) {
            v = *(const float4*)(g_a1 + gn * HID + col4 * 4);
            v.x = fmaxf(v.x + sb1[col4 * 4 + 0], 0.f);
            v.y = fmaxf(v.y + sb1[col4 * 4 + 1], 0.f);
            v.z = fmaxf(v.z + sb1[col4 * 4 + 2], 0.f);
            v.w = fmaxf(v.w + sb1[col4 * 4 + 3], 0.f);
        }
        float* dd = &xs[node][col4 * 4];
        dd[0] = v.x; dd[1] = v.y; dd[2] = v.z; dd[3] = v.w;
    }
    __syncthreads();

    const int cb = (tid & 3) * 8;
    const int ng = tid >> 2;
    float acc[4][8];
    #pragma unroll
    for (int a = 0; a < 4; a++)
        #pragma unroll
        for (int c = 0; c < 8; c++) acc[a][c] = sbb[cb + c];

    #pragma unroll
    for (int k = 0; k < 32; k++) {
        float xv[4];
        #pragma unroll
        for (int a = 0; a < 4; a++) xv[a] = xs[ng * 4 + a][k];
        #pragma unroll
        for (int c = 0; c < 8; c++) {
            float wv = ws[k * HID + cb + c];
            #pragma unroll
            for (int a = 0; a < 4; a++) acc[a][c] += xv[a] * wv;
        }
    }
    #pragma unroll
    for (int a = 0; a < 4; a++) {
        int gn = node0 + ng * 4 + a;
        if (gn < N_NODES) {
            int o = gn * HID + cb;
            *(float4*)(g_u + o)     = make_float4(acc[a][0], acc[a][1], acc[a][2], acc[a][3]);
            *(float4*)(g_u + o + 4) = make_float4(acc[a][4], acc[a][5], acc[a][6], acc[a][7]);
            __half2 h0 = __floats2half2_rn(acc[a][0], acc[a][1]);
            __half2 h1 = __floats2half2_rn(acc[a][2], acc[a][3]);
            __half2 h2 = __floats2half2_rn(acc[a][4], acc[a][5]);
            __half2 h3 = __floats2half2_rn(acc[a][6], acc[a][7]);
            uint4 hp;
            hp.x = *(unsigned*)&h0; hp.y = *(unsigned*)&h1;
            hp.z = *(unsigned*)&h2; hp.w = *(unsigned*)&h3;
            *(uint4*)(g_uh + o) = hp;
        }
    }
}

// ---------------- fused gather-agg + scalar head, layer 2 ------------------
__global__ void __launch_bounds__(256) agg_mlp2(const float* __restrict__ b2a) {
    int warp0 = blockIdx.x * 8 + (threadIdx.x >> 5);
    int lane  = threadIdx.x & 31;
    int g     = lane >> 3;
    int j     = lane & 7;
    int n0    = warp0 * NODES_PER_WARP;

    float4 b2 = *(const float4*)(b2a + j * 4);
    float4 wv = *(const float4*)(g_Wv + j * 4);

    #pragma unroll
    for (int q = 0; q < NODES_PER_WARP; q++) {
        int n = n0 + q;
        if (n >= N_NODES) return;
        int d = g_deg[n];
        float4 acc = gather4h(g_uh, g_ell + n * CAP, d, lane, g, j);
        if (g == 0) {
            float4 v = *(const float4*)(g_u + n * HID + j * 4);
            acc.x += v.x; acc.y += v.y; acc.z += v.z; acc.w += v.w;
        }
        xor_reduce4(acc);

        float p = fmaxf(acc.x + b2.x, 0.f) * wv.x
                + fmaxf(acc.y + b2.y, 0.f) * wv.y
                + fmaxf(acc.z + b2.z, 0.f) * wv.z
                + fmaxf(acc.w + b2.w, 0.f) * wv.w;
        p += __shfl_xor_sync(FULL, p, 1);
        p += __shfl_xor_sync(FULL, p, 2);
        p += __shfl_xor_sync(FULL, p, 4);
        if (lane == 0) g_t[n] = p + g_bv;
    }
}

// ---------------- final scalar gather: out = t[n] + sum t[src] + b3 --------
__global__ void __launch_bounds__(256) agg_final(const float* __restrict__ b3,
                                                 float* __restrict__ out) {
    int warp0 = blockIdx.x * 8 + (threadIdx.x >> 5);
    int lane  = threadIdx.x & 31;
    int n0    = warp0 * NODES_PER_WARP;
    #pragma unroll
    for (int q = 0; q < NODES_PER_WARP; q++) {
        int n = n0 + q;
        if (n >= N_NODES) return;
        int d = g_deg[n];
        const int* row = g_ell + n * CAP;
        float acc = 0.f;
        for (int i = lane; i < d; i += 32) acc += __ldg(g_t + __ldg(row + i));
        #pragma unroll
        for (int o = 16; o > 0; o >>= 1)
            acc += __shfl_xor_sync(FULL, acc, o);
        if (lane == 0) out[n] = g_t[n] + acc + b3[0];
    }
}

// ---------------- launch ---------------------------------------------------
extern "C" void kernel_launch(void* const* d_in, const int* in_sizes, int n_in,
                              void* d_out, int out_size) {
    const float* x   = (const float*)d_in[0];
    const int*   ei  = (const int*)d_in[1];
    const float* w1a = (const float*)d_in[2];
    const float* b1a = (const float*)d_in[3];
    const float* w1b = (const float*)d_in[4];
    const float* b1b = (const float*)d_in[5];
    const float* w2a = (const float*)d_in[6];
    const float* b2a = (const float*)d_in[7];
    const float* w2b = (const float*)d_in[8];
    const float* b2b = (const float*)d_in[9];
    const float* w3  = (const float*)d_in[10];
    const float* b3  = (const float*)d_in[11];
    float* out = (float*)d_out;

    void* deg_ptr = nullptr;
    cudaGetSymbolAddress(&deg_ptr, g_deg);
    cudaMemsetAsync(deg_ptr, 0, N_NODES * sizeof(int));

    const int nwarps_grid = (N_NODES + NODES_PER_WARP - 1) / NODES_PER_WARP;
    const int agg_blocks  = (nwarps_grid + 7) / 8;

    build_ell<<<NB_BUILD + 1, 256>>>(ei, w1b, w2a, b1b, w2b, w3, b2b);
    gemm1<<<(N_NODES + 255) / 256, 256>>>(x, w1a);
    agg1<<<agg_blocks, 256>>>();
    mlp1<<<(N_NODES + 255) / 256, 256>>>(b1a);
    agg_mlp2<<<agg_blocks, 256>>>(b2a);
    agg_final<<<agg_blocks, 256>>>(b3, out);
}